// round 3
// baseline (speedup 1.0000x reference)
#include <cuda_runtime.h>
#include <float.h>

#define C_DIM 512
#define H_DIM 50
#define W_DIM 75
#define HW_DIM (H_DIM * W_DIM)
#define NROI 512
#define PRE 14
#define NSAMP (PRE * PRE)   // 196
#define PADC 132            // stage row stride in floats

// channels-last scratch copy of the feature map: [H*W, C]
__device__ __align__(16) float g_featT[HW_DIM * C_DIM];

// -------------------------------------------------------------------------
// Tiled transpose: bottom [C, H*W] -> g_featT [H*W, C]
// -------------------------------------------------------------------------
__global__ void transpose_kernel(const float* __restrict__ in) {
    __shared__ float tile[32][33];
    int hw0 = blockIdx.x * 32;
    int c0  = blockIdx.y * 32;
    int tx = threadIdx.x, ty = threadIdx.y;

    #pragma unroll
    for (int j = 0; j < 32; j += 8) {
        int hw = hw0 + tx;
        int c  = c0 + ty + j;
        if (hw < HW_DIM) tile[ty + j][tx] = in[c * HW_DIM + hw];
    }
    __syncthreads();
    #pragma unroll
    for (int j = 0; j < 32; j += 8) {
        int hw = hw0 + ty + j;
        int c  = c0 + tx;
        if (hw < HW_DIM) g_featT[hw * C_DIM + c] = tile[tx][ty + j];
    }
}

// -------------------------------------------------------------------------
// Main kernel: grid (512 rois, 4 channel-quarters), 128 threads (4 warps).
// Lane owns 4 consecutive channels (float4); warp covers the 128-channel
// quarter; the 4 warps split the 49 output pixels round-robin.
// Per-sample combined tables: corner-offset sums (float4 units) + weight
// products, so each bilinear sample is 4 LDG.128 + 4-term FMA dot.
// -------------------------------------------------------------------------
__global__ __launch_bounds__(128, 7) void roi_pool_kernel(
    const float* __restrict__ rois, float* __restrict__ out) {

    __shared__ float sw[4][PRE];     // wx0, wx1, wy0, wy1 (border-zeroed)
    __shared__ int   so[4][PRE];     // xo0, xo1, yo0, yo1 (float4 units)
    __shared__ __align__(16) int4   soff[NSAMP];
    __shared__ __align__(16) float4 swt[NSAMP];
    __shared__ __align__(16) float  stage[49 * PADC];

    const int n = blockIdx.x;
    const int t = threadIdx.x;

    // ---- stage 1: per-axis corner tables (threads 0..27) ----
    if (t < 2 * PRE) {
        const int axis = (t >= PRE);          // 0 = x, 1 = y
        const int i = axis ? (t - PRE) : t;
        const float lo = rois[n * 5 + (axis ? 2 : 1)] * (1.0f / 16.0f);
        const float hi = rois[n * 5 + (axis ? 4 : 3)] * (1.0f / 16.0f);
        const int D = axis ? H_DIM : W_DIM;

        // replicate reference math exactly
        float s  = (hi - lo) / (float)(D - 1);
        float tt = (lo + hi - (float)(D - 1)) / (float)(D - 1);
        float base = -1.0f + (float)i * (2.0f / 13.0f);
        float g  = s * base + tt;
        float xc = (g + 1.0f) * 0.5f * (float)(D - 1);

        float f0 = floorf(xc);
        int   i0 = (int)f0;
        float w1 = xc - f0;
        float w0 = 1.0f - w1;
        float v0 = (i0 >= 0 && i0 <= D - 1) ? 1.0f : 0.0f;
        float v1 = (i0 + 1 >= 0 && i0 + 1 <= D - 1) ? 1.0f : 0.0f;
        int c0 = min(max(i0, 0), D - 1);
        int c1 = min(max(i0 + 1, 0), D - 1);

        int mul = axis ? (W_DIM * (C_DIM / 4)) : (C_DIM / 4);
        so[2 * axis + 0][i] = c0 * mul;
        so[2 * axis + 1][i] = c1 * mul;
        sw[2 * axis + 0][i] = w0 * v0;
        sw[2 * axis + 1][i] = w1 * v1;
    }
    __syncthreads();

    // ---- stage 2: combined per-sample tables (196 samples) ----
    for (int s = t; s < NSAMP; s += 128) {
        int sy = s / PRE;
        int sx = s - sy * PRE;
        int yo0 = so[2][sy], yo1 = so[3][sy];
        int xo0 = so[0][sx], xo1 = so[1][sx];
        float wy0 = sw[2][sy], wy1 = sw[3][sy];
        float wx0 = sw[0][sx], wx1 = sw[1][sx];
        soff[s] = make_int4(yo0 + xo0, yo0 + xo1, yo1 + xo0, yo1 + xo1);
        swt[s]  = make_float4(wy0 * wx0, wy0 * wx1, wy1 * wx0, wy1 * wx1);
    }
    __syncthreads();

    const int w    = t >> 5;
    const int lane = t & 31;
    const float4* __restrict__ fb =
        (const float4*)g_featT + blockIdx.y * 32 + lane;
    float4* stage4 = (float4*)stage;

    for (int p = w; p < 49; p += 4) {
        const int py = p / 7;
        const int px = p - py * 7;
        const int s0 = (2 * py) * PRE + 2 * px;

        float4 m = make_float4(-FLT_MAX, -FLT_MAX, -FLT_MAX, -FLT_MAX);

        #pragma unroll
        for (int k = 0; k < 4; k++) {
            const int s = s0 + (k >> 1) * PRE + (k & 1);
            const int4   o  = soff[s];
            const float4 wt = swt[s];

            float4 f0 = fb[o.x];
            float4 f1 = fb[o.y];
            float4 f2 = fb[o.z];
            float4 f3 = fb[o.w];

            float4 v;
            v.x = fmaf(f0.x, wt.x, fmaf(f1.x, wt.y, fmaf(f2.x, wt.z, f3.x * wt.w)));
            v.y = fmaf(f0.y, wt.x, fmaf(f1.y, wt.y, fmaf(f2.y, wt.z, f3.y * wt.w)));
            v.z = fmaf(f0.z, wt.x, fmaf(f1.z, wt.y, fmaf(f2.z, wt.z, f3.z * wt.w)));
            v.w = fmaf(f0.w, wt.x, fmaf(f1.w, wt.y, fmaf(f2.w, wt.z, f3.w * wt.w)));
            m.x = fmaxf(m.x, v.x);
            m.y = fmaxf(m.y, v.y);
            m.z = fmaxf(m.z, v.z);
            m.w = fmaxf(m.w, v.w);
        }
        // pixel-major stage: STG.128 quarter-warp phases are contiguous
        stage4[p * (PADC / 4) + lane] = m;
    }
    __syncthreads();

    // ---- coalesced writeback: 6272 floats, idx = t + k*128 walked incrementally
    float* __restrict__ ob = out + (size_t)n * (C_DIM * 49)
                                 + (size_t)blockIdx.y * (128 * 49);
    int c = t / 49;
    int p = t - c * 49;
    #pragma unroll 7
    for (int k = 0; k < 49; k++) {
        ob[t + k * 128] = stage[p * PADC + c];
        p += 30; c += 2;              // advance by 128 = 2*49 + 30
        if (p >= 49) { p -= 49; c += 1; }
    }
}

// -------------------------------------------------------------------------
extern "C" void kernel_launch(void* const* d_in, const int* in_sizes, int n_in,
                              void* d_out, int out_size) {
    const float* bottom = (const float*)d_in[0];
    const float* rois   = (const float*)d_in[1];
    if (n_in >= 2 && in_sizes[0] == NROI * 5) {
        bottom = (const float*)d_in[1];
        rois   = (const float*)d_in[0];
    }
    float* out = (float*)d_out;

    dim3 tgrid((HW_DIM + 31) / 32, C_DIM / 32);
    transpose_kernel<<<tgrid, dim3(32, 8)>>>(bottom);

    dim3 rgrid(NROI, 4);
    roi_pool_kernel<<<rgrid, 128>>>(rois, out);
}

// round 4
// speedup vs baseline: 1.1032x; 1.1032x over previous
#include <cuda_runtime.h>
#include <float.h>

#define C_DIM 512
#define H_DIM 50
#define W_DIM 75
#define HW_DIM (H_DIM * W_DIM)
#define NROI 512
#define PRE 14
#define PADC 132   // stage row stride in floats (33 float4)

// channels-last scratch copy of the feature map: [H*W, C]
__device__ __align__(16) float g_featT[HW_DIM * C_DIM];

// -------------------------------------------------------------------------
// Tiled transpose: bottom [C, H*W] -> g_featT [H*W, C]
// -------------------------------------------------------------------------
__global__ void transpose_kernel(const float* __restrict__ in) {
    __shared__ float tile[32][33];
    int hw0 = blockIdx.x * 32;
    int c0  = blockIdx.y * 32;
    int tx = threadIdx.x, ty = threadIdx.y;

    #pragma unroll
    for (int j = 0; j < 32; j += 8) {
        int hw = hw0 + tx;
        int c  = c0 + ty + j;
        if (hw < HW_DIM) tile[ty + j][tx] = in[c * HW_DIM + hw];
    }
    __syncthreads();
    #pragma unroll
    for (int j = 0; j < 32; j += 8) {
        int hw = hw0 + ty + j;
        int c  = c0 + tx;
        if (hw < HW_DIM) g_featT[hw * C_DIM + c] = tile[tx][ty + j];
    }
}

// -------------------------------------------------------------------------
// Main kernel: grid (512 rois, 4 channel-quarters), 128 threads (4 warps).
// Lane owns 4 consecutive channels (float4); warp covers the 128-channel
// quarter; the 4 warps split the 49 output pixels round-robin, TWO pixels
// per iteration (interleaved at sample granularity for 2x MLP).
// -------------------------------------------------------------------------
__global__ __launch_bounds__(128, 6) void roi_pool_kernel(
    const float* __restrict__ rois, float* __restrict__ out) {

    // Packed per-axis corner tables: (.x = off0 bits, .y = off1 bits,
    //                                 .z = w0, .w = w1), offsets in float4 units.
    __shared__ float4 tabx[PRE], taby[PRE];
    __shared__ __align__(16) float stage[49 * PADC];

    const int n = blockIdx.x;
    const int t = threadIdx.x;

    // ---- per-ROI corner tables (threads 0..27) ----
    if (t < 2 * PRE) {
        const int axis = (t >= PRE);          // 0 = x, 1 = y
        const int i = axis ? (t - PRE) : t;
        const float lo = rois[n * 5 + (axis ? 2 : 1)] * (1.0f / 16.0f);
        const float hi = rois[n * 5 + (axis ? 4 : 3)] * (1.0f / 16.0f);
        const int D = axis ? H_DIM : W_DIM;

        // replicate reference math exactly
        float s  = (hi - lo) / (float)(D - 1);
        float tt = (lo + hi - (float)(D - 1)) / (float)(D - 1);
        float base = -1.0f + (float)i * (2.0f / 13.0f);
        float g  = s * base + tt;
        float xc = (g + 1.0f) * 0.5f * (float)(D - 1);

        float f0 = floorf(xc);
        int   i0 = (int)f0;
        float w1 = xc - f0;
        float w0 = 1.0f - w1;
        float v0 = (i0 >= 0 && i0 <= D - 1) ? 1.0f : 0.0f;
        float v1 = (i0 + 1 >= 0 && i0 + 1 <= D - 1) ? 1.0f : 0.0f;
        int c0 = min(max(i0, 0), D - 1);
        int c1 = min(max(i0 + 1, 0), D - 1);

        int mul = axis ? (W_DIM * (C_DIM / 4)) : (C_DIM / 4);
        float4 e;
        e.x = __int_as_float(c0 * mul);
        e.y = __int_as_float(c1 * mul);
        e.z = w0 * v0;
        e.w = w1 * v1;
        if (axis) taby[i] = e; else tabx[i] = e;
    }
    __syncthreads();

    const int w    = t >> 5;
    const int lane = t & 31;
    const float4* __restrict__ fb =
        (const float4*)g_featT + blockIdx.y * 32 + lane;
    float4* stage4 = (float4*)stage;

    // warp w owns pixels p ≡ w (mod 4); process two per iteration.
    for (int pa = w; pa < 49; pa += 8) {
        const int pbr = pa + 4;
        const bool hasb = (pbr < 49);
        const int pb = hasb ? pbr : pa;     // clamp: duplicate work, no branch

        const int pya = pa / 7, pxa = pa - pya * 7;
        const int pyb = pb / 7, pxb = pb - pyb * 7;

        const float4 ax0 = tabx[2 * pxa], ax1 = tabx[2 * pxa + 1];
        const float4 ay0 = taby[2 * pya], ay1 = taby[2 * pya + 1];
        const float4 bx0 = tabx[2 * pxb], bx1 = tabx[2 * pxb + 1];
        const float4 by0 = taby[2 * pyb], by1 = taby[2 * pyb + 1];

        float4 ma = make_float4(-FLT_MAX, -FLT_MAX, -FLT_MAX, -FLT_MAX);
        float4 mb = ma;

        #pragma unroll
        for (int k = 0; k < 4; k++) {
            const int dy = k >> 1, dx = k & 1;

            const float4 tya = dy ? ay1 : ay0;
            const float4 txa = dx ? ax1 : ax0;
            const float4 tyb = dy ? by1 : by0;
            const float4 txb = dx ? bx1 : bx0;

            const int aoy0 = __float_as_int(tya.x), aoy1 = __float_as_int(tya.y);
            const int aox0 = __float_as_int(txa.x), aox1 = __float_as_int(txa.y);
            const int boy0 = __float_as_int(tyb.x), boy1 = __float_as_int(tyb.y);
            const int box0 = __float_as_int(txb.x), box1 = __float_as_int(txb.y);

            // 8 independent gathers in flight
            float4 a00 = fb[aoy0 + aox0];
            float4 a01 = fb[aoy0 + aox1];
            float4 a10 = fb[aoy1 + aox0];
            float4 a11 = fb[aoy1 + aox1];
            float4 b00 = fb[boy0 + box0];
            float4 b01 = fb[boy0 + box1];
            float4 b10 = fb[boy1 + box0];
            float4 b11 = fb[boy1 + box1];

            const float awx0 = txa.z, awx1 = txa.w, awy0 = tya.z, awy1 = tya.w;
            const float bwx0 = txb.z, bwx1 = txb.w, bwy0 = tyb.z, bwy1 = tyb.w;

            float4 va, vb;
            va.x = (a00.x * awx0 + a01.x * awx1) * awy0 + (a10.x * awx0 + a11.x * awx1) * awy1;
            va.y = (a00.y * awx0 + a01.y * awx1) * awy0 + (a10.y * awx0 + a11.y * awx1) * awy1;
            va.z = (a00.z * awx0 + a01.z * awx1) * awy0 + (a10.z * awx0 + a11.z * awx1) * awy1;
            va.w = (a00.w * awx0 + a01.w * awx1) * awy0 + (a10.w * awx0 + a11.w * awx1) * awy1;
            vb.x = (b00.x * bwx0 + b01.x * bwx1) * bwy0 + (b10.x * bwx0 + b11.x * bwx1) * bwy1;
            vb.y = (b00.y * bwx0 + b01.y * bwx1) * bwy0 + (b10.y * bwx0 + b11.y * bwx1) * bwy1;
            vb.z = (b00.z * bwx0 + b01.z * bwx1) * bwy0 + (b10.z * bwx0 + b11.z * bwx1) * bwy1;
            vb.w = (b00.w * bwx0 + b01.w * bwx1) * bwy0 + (b10.w * bwx0 + b11.w * bwx1) * bwy1;

            ma.x = fmaxf(ma.x, va.x);  ma.y = fmaxf(ma.y, va.y);
            ma.z = fmaxf(ma.z, va.z);  ma.w = fmaxf(ma.w, va.w);
            mb.x = fmaxf(mb.x, vb.x);  mb.y = fmaxf(mb.y, vb.y);
            mb.z = fmaxf(mb.z, vb.z);  mb.w = fmaxf(mb.w, vb.w);
        }

        stage4[pa * (PADC / 4) + lane] = ma;
        if (hasb)
            stage4[pbr * (PADC / 4) + lane] = mb;
    }
    __syncthreads();

    // ---- coalesced writeback: 6272 floats, idx = t + k*128 walked incrementally
    float* __restrict__ ob = out + (size_t)n * (C_DIM * 49)
                                 + (size_t)blockIdx.y * (128 * 49);
    int c = t / 49;
    int p = t - c * 49;
    #pragma unroll 7
    for (int k = 0; k < 49; k++) {
        ob[t + k * 128] = stage[p * PADC + c];
        p += 30; c += 2;              // advance by 128 = 2*49 + 30
        if (p >= 49) { p -= 49; c += 1; }
    }
}

// -------------------------------------------------------------------------
extern "C" void kernel_launch(void* const* d_in, const int* in_sizes, int n_in,
                              void* d_out, int out_size) {
    const float* bottom = (const float*)d_in[0];
    const float* rois   = (const float*)d_in[1];
    if (n_in >= 2 && in_sizes[0] == NROI * 5) {
        bottom = (const float*)d_in[1];
        rois   = (const float*)d_in[0];
    }
    float* out = (float*)d_out;

    dim3 tgrid((HW_DIM + 31) / 32, C_DIM / 32);
    transpose_kernel<<<tgrid, dim3(32, 8)>>>(bottom);

    dim3 rgrid(NROI, 4);
    roi_pool_kernel<<<rgrid, 128>>>(rois, out);
}